// round 11
// baseline (speedup 1.0000x reference)
#include <cuda_runtime.h>
#include <cuda_bf16.h>
#include <math.h>
#include <stdint.h>

// Problem constants
#define B_   4096
#define D_   512
#define K_   4096
#define N_   131072
#define R_   3
#define INV_T 14.2857142857142857f   // 1/0.07
#define LOG2E 1.4426950408889634f

// ---------------- scratch (device globals; no allocation allowed) -------------
__device__ __nv_bfloat16 g_anorm[B_*D_];
__device__ __nv_bfloat16 g_fnorm[B_*D_];
__device__ __nv_bfloat16 g_Pa[R_*B_*D_];
__device__ __nv_bfloat16 g_Pf[R_*B_*D_];
__device__ float g_densa[R_*B_];
__device__ float g_densf[R_*B_];
__device__ float g_idensa[R_*B_];
__device__ float g_idensf[R_*B_];
__device__ float g_rho[B_];
__device__ float g_diag_vf[B_];
__device__ float g_diagp_vf[R_*B_];
__device__ float g_diagp_fv[R_*B_];
__device__ float g_rowsum[B_];
__device__ float g_colsum[B_];
__device__ float g_psum_vf[R_*B_];
__device__ float g_psum_fv[R_*B_];
__device__ float g_w[B_];
__device__ float g_acc[3];            // sw, svf, sfv

// ---------------- helpers ----------------------------------------------------
template<int NT>
__device__ __forceinline__ float blockReduceSum(float v, volatile float* sh) {
    #pragma unroll
    for (int o = 16; o > 0; o >>= 1) v += __shfl_xor_sync(0xffffffffu, v, o);
    int lane = threadIdx.x & 31;
    int wid  = threadIdx.x >> 5;
    if (lane == 0) sh[wid] = v;
    __syncthreads();
    if (threadIdx.x == 0) {
        float r = 0.f;
        #pragma unroll
        for (int w = 0; w < NT/32; w++) r += sh[w];
        sh[0] = r;
    }
    __syncthreads();
    float r = sh[0];
    __syncthreads();
    return r;
}

__device__ __forceinline__ float warpReduceSum(float v) {
    #pragma unroll
    for (int o = 16; o > 0; o >>= 1) v += __shfl_xor_sync(0xffffffffu, v, o);
    return v;
}

__device__ __forceinline__ float dot4(float4 a, float4 b) {
    return a.x*b.x + a.y*b.y + a.z*b.z + a.w*b.w;
}

__device__ __forceinline__ float ex2(float x) {
    float y;
    asm("ex2.approx.ftz.f32 %0, %1;" : "=f"(y) : "f"(x));
    return y;
}

__device__ __forceinline__ uint2 pack_bf16x4(float4 v) {
    __nv_bfloat162 lo = __floats2bfloat162_rn(v.x, v.y);
    __nv_bfloat162 hi = __floats2bfloat162_rn(v.z, v.w);
    uint2 u;
    u.x = *(uint32_t*)&lo;
    u.y = *(uint32_t*)&hi;
    return u;
}

#define CP_ASYNC16(dst, src) \
    asm volatile("cp.async.cg.shared.global [%0], [%1], 16;" :: "r"(dst), "l"(src))
#define CP_COMMIT() asm volatile("cp.async.commit_group;" ::: "memory")
#define CP_WAIT1()  asm volatile("cp.async.wait_group 1;"  ::: "memory")

static __device__ __forceinline__ uint32_t smem_u32(const void* p) {
    uint32_t a;
    asm("{ .reg .u64 t; cvta.to.shared.u64 t, %1; cvt.u32.u64 %0, t; }"
        : "=r"(a) : "l"(p));
    return a;
}

#define LDSM_X4(r0, r1, r2, r3, addr) \
    asm volatile("ldmatrix.sync.aligned.m8n8.x4.shared.b16 {%0,%1,%2,%3}, [%4];" \
                 : "=r"(r0), "=r"(r1), "=r"(r2), "=r"(r3) : "r"(addr))

__device__ __forceinline__ void mma_bf16(float& d0, float& d1, float& d2, float& d3,
                                         uint32_t a0, uint32_t a1, uint32_t a2, uint32_t a3,
                                         uint32_t b0, uint32_t b1) {
    asm volatile(
        "mma.sync.aligned.m16n8k16.row.col.f32.bf16.bf16.f32 "
        "{%0,%1,%2,%3}, {%4,%5,%6,%7}, {%8,%9}, {%0,%1,%2,%3};"
        : "+f"(d0), "+f"(d1), "+f"(d2), "+f"(d3)
        : "r"(a0), "r"(a1), "r"(a2), "r"(a3), "r"(b0), "r"(b1));
}

// ---------------- kernel 1: zero + normalize + gather + rho/diag prep --------
__global__ void __launch_bounds__(256) prep_kernel(
        const float* __restrict__ audio,
        const float* __restrict__ frame,
        const float* __restrict__ acent,
        const float* __restrict__ adens,
        const float* __restrict__ fcent,
        const float* __restrict__ fdens,
        const int*   __restrict__ vidx,
        const int*   __restrict__ ai2c,
        const int*   __restrict__ fi2c) {
    int gid = blockIdx.x * 256 + threadIdx.x;
    if (gid < B_) { g_rowsum[gid] = 0.f; g_colsum[gid] = 0.f; }
    if (gid < R_*B_) { g_psum_vf[gid] = 0.f; g_psum_fv[gid] = 0.f; }
    if (gid < 3) g_acc[gid] = 0.f;

    int w    = threadIdx.x >> 5;
    int lane = threadIdx.x & 31;
    int i    = blockIdx.x * 8 + w;

    const float4* a4 = (const float4*)(audio + (size_t)i*D_);
    const float4* f4 = (const float4*)(frame + (size_t)i*D_);
    float4 a[4], f[4];
    #pragma unroll
    for (int q = 0; q < 4; q++) { a[q] = a4[q*32 + lane]; f[q] = f4[q*32 + lane]; }

    float sa = 0.f, sf = 0.f, saf = 0.f;
    #pragma unroll
    for (int q = 0; q < 4; q++) {
        sa  += dot4(a[q], a[q]);
        sf  += dot4(f[q], f[q]);
        saf += dot4(a[q], f[q]);
    }
    sa = warpReduceSum(sa); sf = warpReduceSum(sf); saf = warpReduceSum(saf);

    float ascale = 1.f / fmaxf(sqrtf(sa), 1e-12f);
    float fscale = 1.f / fmaxf(sqrtf(sf), 1e-12f);

    uint2* anOut = (uint2*)(g_anorm + (size_t)i*D_);
    uint2* fnOut = (uint2*)(g_fnorm + (size_t)i*D_);
    #pragma unroll
    for (int q = 0; q < 4; q++) {
        anOut[q*32 + lane] = pack_bf16x4(make_float4(a[q].x*ascale, a[q].y*ascale,
                                                     a[q].z*ascale, a[q].w*ascale));
        fnOut[q*32 + lane] = pack_bf16x4(make_float4(f[q].x*fscale, f[q].y*fscale,
                                                     f[q].z*fscale, f[q].w*fscale));
    }

    float rho = saf * ascale * fscale;
    if (lane == 0) g_diag_vf[i] = rho * INV_T;

    int vi = vidx[i];
    #pragma unroll
    for (int r = 0; r < R_; r++) {
        int pa = ai2c[r*N_ + vi];
        int pf = fi2c[r*N_ + vi];
        const float4* ca4 = (const float4*)(acent + ((size_t)r*K_ + pa)*D_);
        const float4* cf4 = (const float4*)(fcent + ((size_t)r*K_ + pf)*D_);
        float4 ca[4], cf[4];
        #pragma unroll
        for (int q = 0; q < 4; q++) { ca[q] = ca4[q*32 + lane]; cf[q] = cf4[q*32 + lane]; }

        float c1 = 0.f, c2 = 0.f, c3 = 0.f, c4 = 0.f, c5 = 0.f;
        #pragma unroll
        for (int q = 0; q < 4; q++) {
            c1 += dot4(ca[q], ca[q]);
            c2 += dot4(cf[q], cf[q]);
            c3 += dot4(ca[q], cf[q]);
            c4 += dot4(a[q],  cf[q]);
            c5 += dot4(f[q],  ca[q]);
        }
        c1 = warpReduceSum(c1); c2 = warpReduceSum(c2); c3 = warpReduceSum(c3);
        c4 = warpReduceSum(c4); c5 = warpReduceSum(c5);

        float cascale = 1.f / fmaxf(sqrtf(c1), 1e-12f);
        float cfscale = 1.f / fmaxf(sqrtf(c2), 1e-12f);

        uint2* paOut = (uint2*)(g_Pa + ((size_t)r*B_ + i)*D_);
        uint2* pfOut = (uint2*)(g_Pf + ((size_t)r*B_ + i)*D_);
        #pragma unroll
        for (int q = 0; q < 4; q++) {
            paOut[q*32 + lane] = pack_bf16x4(make_float4(ca[q].x*cascale, ca[q].y*cascale,
                                                         ca[q].z*cascale, ca[q].w*cascale));
            pfOut[q*32 + lane] = pack_bf16x4(make_float4(cf[q].x*cfscale, cf[q].y*cfscale,
                                                         cf[q].z*cfscale, cf[q].w*cfscale));
        }

        rho -= c3;
        if (lane == 0) {
            float da = adens[r*K_ + pa];
            float df = fdens[r*K_ + pf];
            g_densa[r*B_ + i]    = da;
            g_densf[r*B_ + i]    = df;
            g_idensa[r*B_ + i]   = 1.f / da;
            g_idensf[r*B_ + i]   = 1.f / df;
            g_diagp_vf[r*B_ + i] = c4 * ascale * cfscale;
            g_diagp_fv[r*B_ + i] = c5 * fscale * cascale;
        }
    }
    if (lane == 0) g_rho[i] = rho;
}

// ---------------- kernel 2: PERSISTENT bf16 GEMM + fused exp-sum epilogue ----
// 128x128 CTA tile, 8 warps 2(M)x4(N), warp tile 64x32, BK=64, 3-stage
// cp.async pipeline with single __syncthreads per chunk. Persistent: each CTA
// loops over tiles; the chunk stream crosses tile boundaries, so chunks 0,1 of
// tile i+1 are prefetched during chunks 6,7 of tile i, and the epilogue of
// tile i overlaps those loads.
#define TM 128
#define TN 128
#define BK 64
#define NCHUNK (D_/BK)
#define SROWB 144
#define NTILES (7*32*32)               // 7168

#define SZ_A (TM*SROWB)                // 18432
#define SZ_B (TN*SROWB)                // 18432
#define SZ_STAGE (SZ_A + SZ_B)         // 36864
#define SO_DENS (3*SZ_STAGE)
#define GEMM_SMEM (SO_DENS + 132*4)

struct TileP {
    const __nv_bfloat16 *A, *Bm;
    int rowBase, colBase, z;
};

__device__ __forceinline__ TileP tile_params(int tile) {
    TileP p;
    p.z = tile >> 10;                   // / (32*32)
    int rem = tile & 1023;
    p.rowBase = (rem >> 5) * TM;
    p.colBase = (rem & 31) * TN;
    if (p.z == 0)      { p.A = g_anorm; p.Bm = g_fnorm; }
    else if (p.z <= 3) { p.A = g_anorm; p.Bm = g_Pf + (size_t)(p.z-1)*B_*D_; }
    else               { p.A = g_fnorm; p.Bm = g_Pa + (size_t)(p.z-4)*B_*D_; }
    return p;
}

__device__ __forceinline__ void load_stage(uint32_t stBase,
                                           const __nv_bfloat16* __restrict__ A,
                                           const __nv_bfloat16* __restrict__ Bm,
                                           int rowBase, int colBase, int k0, int t) {
    uint32_t aBase = stBase;
    uint32_t bBase = stBase + SZ_A;
    #pragma unroll
    for (int q = 0; q < 4; q++) {
        int slot = t + q*256;
        int r = slot >> 3, s = slot & 7;
        CP_ASYNC16(aBase + r*SROWB + s*16,
                   A + (size_t)(rowBase + r)*D_ + k0 + s*8);
    }
    #pragma unroll
    for (int q = 0; q < 4; q++) {
        int slot = t + q*256;
        int r = slot >> 3, s = slot & 7;
        CP_ASYNC16(bBase + r*SROWB + s*16,
                   Bm + (size_t)(colBase + r)*D_ + k0 + s*8);
    }
}

__global__ void __launch_bounds__(256) gemm_kernel() {
    extern __shared__ char smem[];
    uint32_t sb = smem_u32(smem);
    int t    = threadIdx.x;
    int wid  = t >> 5;
    int lane = t & 31;
    int g    = lane >> 2;
    int tq   = lane & 3;
    int mbase = (wid & 1) * 64;
    int nbase = (wid >> 1) * 32;

    int lq = lane >> 3, lr = lane & 7;
    uint32_t aOff[4];
    #pragma unroll
    for (int Mt = 0; Mt < 4; Mt++)
        aOff[Mt] = (mbase + Mt*16 + (lq & 1)*8 + lr)*SROWB + (lq >> 1)*16;
    uint32_t bOff[2];
    #pragma unroll
    for (int p = 0; p < 2; p++)
        bOff[p] = SZ_A + (nbase + p*16 + (lq >> 1)*8 + lr)*SROWB + (lq & 1)*16;

    int stride = gridDim.x;
    int tile = blockIdx.x;
    if (tile >= NTILES) return;

    TileP cur = tile_params(tile);
    load_stage(sb + 0*SZ_STAGE, cur.A, cur.Bm, cur.rowBase, cur.colBase, 0,  t);
    CP_COMMIT();
    load_stage(sb + 1*SZ_STAGE, cur.A, cur.Bm, cur.rowBase, cur.colBase, BK, t);
    CP_COMMIT();

    int stage = 0;
    float* sdens = (float*)(smem + SO_DENS);

    #pragma unroll 1
    while (true) {
        int nextTile = tile + stride;
        bool hasNext = nextTile < NTILES;
        TileP nxt;
        if (hasNext) nxt = tile_params(nextTile);

        float acc[4][4][4];
        #pragma unroll
        for (int i = 0; i < 4; i++)
            #pragma unroll
            for (int j = 0; j < 4; j++) {
                acc[i][j][0] = 0.f; acc[i][j][1] = 0.f;
                acc[i][j][2] = 0.f; acc[i][j][3] = 0.f;
            }

        #pragma unroll 1
        for (int c = 0; c < NCHUNK; c++) {
            CP_WAIT1();
            __syncthreads();
            uint32_t stB = sb + stage*SZ_STAGE;

            #pragma unroll
            for (int ks = 0; ks < 4; ks++) {
                uint32_t af[4][4], bf[2][4];
                #pragma unroll
                for (int Mt = 0; Mt < 4; Mt++)
                    LDSM_X4(af[Mt][0], af[Mt][1], af[Mt][2], af[Mt][3],
                            stB + aOff[Mt] + ks*32);
                #pragma unroll
                for (int p = 0; p < 2; p++)
                    LDSM_X4(bf[p][0], bf[p][1], bf[p][2], bf[p][3],
                            stB + bOff[p] + ks*32);
                #pragma unroll
                for (int Mt = 0; Mt < 4; Mt++)
                    #pragma unroll
                    for (int Nt = 0; Nt < 4; Nt++)
                        mma_bf16(acc[Mt][Nt][0], acc[Mt][Nt][1],
                                 acc[Mt][Nt][2], acc[Mt][Nt][3],
                                 af[Mt][0], af[Mt][1], af[Mt][2], af[Mt][3],
                                 bf[Nt>>1][(Nt&1)*2], bf[Nt>>1][(Nt&1)*2 + 1]);
            }

            int pstage = stage + 2; if (pstage >= 3) pstage -= 3;
            int pc = c + 2;
            if (pc < NCHUNK) {
                load_stage(sb + pstage*SZ_STAGE, cur.A, cur.Bm,
                           cur.rowBase, cur.colBase, pc*BK, t);
            } else if (hasNext) {
                load_stage(sb + pstage*SZ_STAGE, nxt.A, nxt.Bm,
                           nxt.rowBase, nxt.colBase, (pc - NCHUNK)*BK, t);
            }
            CP_COMMIT();
            stage++; if (stage == 3) stage = 0;
        }

        // -------- epilogue for `tile` (overlaps next tile's in-flight loads) --
        int z = cur.z;
        const float* idens = nullptr;
        float* rowAcc;
        if (z == 0)      { rowAcc = g_rowsum; }
        else if (z <= 3) { idens = g_idensf + (z-1)*B_; rowAcc = g_psum_vf + (z-1)*B_; }
        else             { idens = g_idensa + (z-4)*B_; rowAcc = g_psum_fv + (z-4)*B_; }

        float d0inv = 0.f;
        if (z != 0) {
            for (int i = t; i < TN + 2; i += 256) {
                int gidx = cur.colBase + i;
                sdens[i] = (gidx < B_) ? idens[gidx] * LOG2E : 1.f;
            }
            d0inv = idens[0] * LOG2E;
        }
        __syncthreads();

        if (z == 0) {
            const float k1 = INV_T * LOG2E;
            float rowp[4][2] = {};
            float colp[4][2] = {};
            #pragma unroll
            for (int Mt = 0; Mt < 4; Mt++)
                #pragma unroll
                for (int Nt = 0; Nt < 4; Nt++) {
                    float e00 = ex2(acc[Mt][Nt][0] * k1);
                    float e01 = ex2(acc[Mt][Nt][1] * k1);
                    float e10 = ex2(acc[Mt][Nt][2] * k1);
                    float e11 = ex2(acc[Mt][Nt][3] * k1);
                    rowp[Mt][0] += e00 + e01;
                    rowp[Mt][1] += e10 + e11;
                    colp[Nt][0] += e00 + e10;
                    colp[Nt][1] += e01 + e11;
                }
            #pragma unroll
            for (int Mt = 0; Mt < 4; Mt++)
                #pragma unroll
                for (int h = 0; h < 2; h++) {
                    float v = rowp[Mt][h];
                    v += __shfl_xor_sync(0xffffffffu, v, 1);
                    v += __shfl_xor_sync(0xffffffffu, v, 2);
                    if (tq == 0)
                        atomicAdd(&rowAcc[cur.rowBase + mbase + Mt*16 + g + h*8], v);
                }
            #pragma unroll
            for (int Nt = 0; Nt < 4; Nt++)
                #pragma unroll
                for (int h = 0; h < 2; h++) {
                    float v = colp[Nt][h];
                    v += __shfl_xor_sync(0xffffffffu, v, 4);
                    v += __shfl_xor_sync(0xffffffffu, v, 8);
                    v += __shfl_xor_sync(0xffffffffu, v, 16);
                    if (g == 0)
                        atomicAdd(&g_colsum[cur.colBase + nbase + Nt*8 + 2*tq + h], v);
                }
        } else {
            float rowp[4][2] = {};
            #pragma unroll
            for (int Mt = 0; Mt < 4; Mt++) {
                int r0 = cur.rowBase + mbase + Mt*16 + g;
                int r1 = r0 + 8;
                #pragma unroll
                for (int Nt = 0; Nt < 4; Nt++) {
                    int lc = nbase + Nt*8 + 2*tq;
                    int c0 = cur.colBase + lc;
                    int c1 = c0 + 1;
                    float i00 = (c0 < r0) ? sdens[lc+1] : ((c0 > r0) ? sdens[lc]   : d0inv);
                    float i01 = (c1 < r0) ? sdens[lc+2] : ((c1 > r0) ? sdens[lc+1] : d0inv);
                    float i10 = (c0 < r1) ? sdens[lc+1] : ((c0 > r1) ? sdens[lc]   : d0inv);
                    float i11 = (c1 < r1) ? sdens[lc+2] : ((c1 > r1) ? sdens[lc+1] : d0inv);
                    rowp[Mt][0] += ex2(acc[Mt][Nt][0] * i00) + ex2(acc[Mt][Nt][1] * i01);
                    rowp[Mt][1] += ex2(acc[Mt][Nt][2] * i10) + ex2(acc[Mt][Nt][3] * i11);
                }
            }
            #pragma unroll
            for (int Mt = 0; Mt < 4; Mt++)
                #pragma unroll
                for (int h = 0; h < 2; h++) {
                    float v = rowp[Mt][h];
                    v += __shfl_xor_sync(0xffffffffu, v, 1);
                    v += __shfl_xor_sync(0xffffffffu, v, 2);
                    if (tq == 0)
                        atomicAdd(&rowAcc[cur.rowBase + mbase + Mt*16 + g + h*8], v);
                }
        }

        if (!hasNext) break;
        tile = nextTile;
        cur = nxt;
    }
}

// ---------------- kernel 3: stats + pdf + rank-cumsum weights (warp/row) -----
__global__ void __launch_bounds__(256) weight_kernel() {
    __shared__ float srho[B_];
    __shared__ float sp[B_];
    __shared__ float sh[8];
    int t = threadIdx.x;

    for (int j = t; j < B_; j += 256) srho[j] = g_rho[j];
    __syncthreads();

    float s = 0.f, s2 = 0.f;
    for (int j = t; j < B_; j += 256) {
        float v = srho[j];
        s += v; s2 += v*v;
    }
    s  = blockReduceSum<256>(s,  sh);
    s2 = blockReduceSum<256>(s2, sh);
    float mean = s / (float)B_;
    float var  = fmaxf(s2 / (float)B_ - mean*mean, 0.f);
    float sd   = sqrtf(var);
    float mu    = mean + 0.3f * sd;
    float sigma = sd * sqrtf(2.0f);

    for (int j = t; j < B_; j += 256) {
        float zq = (srho[j] - mu) / sigma;
        sp[j] = ex2(-0.5f * LOG2E * zq * zq);
    }
    __syncthreads();

    int w    = t >> 5;
    int lane = t & 31;
    int i    = blockIdx.x * 8 + w;
    float ri = srho[i];
    float acc = 0.f;
    for (int j = lane; j < B_; j += 32) {
        float rj = srho[j];
        if (rj < ri || (rj == ri && j <= i)) acc += sp[j];
    }
    acc = warpReduceSum(acc);
    if (lane == 0) g_w[i] = acc;
}

// ---------------- kernel 4: assemble losses + weighted partial reduction -----
__global__ void __launch_bounds__(256) final_kernel() {
    __shared__ float sh[8];
    const float coef0 = 1.f/27.f, coef1 = 1.f/9.f, coef2 = 1.f/3.f;
    int i = blockIdx.x * 256 + threadIdx.x;

    float ii_vf = logf(g_rowsum[i]) - g_diag_vf[i];
    float ii_fv = logf(g_colsum[i]) - g_diag_vf[i];
    float ip_vf =
        coef0 * (logf(g_psum_vf[0*B_+i]) - g_diagp_vf[0*B_+i] / g_densf[0*B_]) +
        coef1 * (logf(g_psum_vf[1*B_+i]) - g_diagp_vf[1*B_+i] / g_densf[1*B_]) +
        coef2 * (logf(g_psum_vf[2*B_+i]) - g_diagp_vf[2*B_+i] / g_densf[2*B_]);
    float ip_fv =
        coef0 * (logf(g_psum_fv[0*B_+i]) - g_diagp_fv[0*B_+i] / g_densa[0*B_]) +
        coef1 * (logf(g_psum_fv[1*B_+i]) - g_diagp_fv[1*B_+i] / g_densa[1*B_]) +
        coef2 * (logf(g_psum_fv[2*B_+i]) - g_diagp_fv[2*B_+i] / g_densa[2*B_]);
    float w = g_w[i];
    float sw  = blockReduceSum<256>(w, sh);
    float svf = blockReduceSum<256>(w * (ii_vf + ip_vf), sh);
    float sfv = blockReduceSum<256>(w * (ii_fv + ip_fv), sh);
    if (threadIdx.x == 0) {
        atomicAdd(&g_acc[0], sw);
        atomicAdd(&g_acc[1], svf);
        atomicAdd(&g_acc[2], sfv);
    }
}

__global__ void finalize_kernel(float* __restrict__ out) {
    if (threadIdx.x == 0)
        out[0] = g_acc[1] / g_acc[0] + g_acc[2] / g_acc[0];
}

// ---------------- launch -----------------------------------------------------
extern "C" void kernel_launch(void* const* d_in, const int* in_sizes, int n_in,
                              void* d_out, int out_size) {
    const float* audio = (const float*)d_in[0];
    const float* frame = (const float*)d_in[1];
    const float* acent = (const float*)d_in[2];
    const float* adens = (const float*)d_in[3];
    const float* fcent = (const float*)d_in[4];
    const float* fdens = (const float*)d_in[5];
    const int*   vidx  = (const int*)d_in[6];
    const int*   ai2c  = (const int*)d_in[7];
    const int*   fi2c  = (const int*)d_in[8];
    float* out = (float*)d_out;
    (void)in_sizes; (void)n_in; (void)out_size;

    cudaFuncSetAttribute(gemm_kernel,
                         cudaFuncAttributeMaxDynamicSharedMemorySize, GEMM_SMEM);

    int sms = 148;
    cudaDeviceGetAttribute(&sms, cudaDevAttrMultiProcessorCount, 0);

    prep_kernel<<<B_/8, 256>>>(audio, frame, acent, adens, fcent, fdens,
                               vidx, ai2c, fi2c);
    weight_kernel<<<B_/8, 256>>>();
    gemm_kernel<<<sms, 256, GEMM_SMEM>>>();
    final_kernel<<<B_/256, 256>>>();
    finalize_kernel<<<1, 32>>>(out);
}

// round 12
// speedup vs baseline: 1.3018x; 1.3018x over previous
#include <cuda_runtime.h>
#include <cuda_bf16.h>
#include <math.h>
#include <stdint.h>

// Problem constants
#define B_   4096
#define D_   512
#define K_   4096
#define N_   131072
#define R_   3
#define INV_T 14.2857142857142857f   // 1/0.07
#define LOG2E 1.4426950408889634f

// ---------------- scratch (device globals; no allocation allowed) -------------
__device__ __nv_bfloat16 g_anorm[B_*D_];
__device__ __nv_bfloat16 g_fnorm[B_*D_];
__device__ __nv_bfloat16 g_Pa[R_*B_*D_];
__device__ __nv_bfloat16 g_Pf[R_*B_*D_];
__device__ float g_densa[R_*B_];
__device__ float g_densf[R_*B_];
__device__ float g_idensa[R_*B_];
__device__ float g_idensf[R_*B_];
__device__ float g_rho[B_];
__device__ float g_diag_vf[B_];
__device__ float g_diagp_vf[R_*B_];
__device__ float g_diagp_fv[R_*B_];
__device__ float g_rowsum[B_];
__device__ float g_colsum[B_];
__device__ float g_psum_vf[R_*B_];
__device__ float g_psum_fv[R_*B_];
__device__ float g_w[B_];
__device__ float g_acc[3];            // sw, svf, sfv

// ---------------- helpers ----------------------------------------------------
template<int NT>
__device__ __forceinline__ float blockReduceSum(float v, volatile float* sh) {
    #pragma unroll
    for (int o = 16; o > 0; o >>= 1) v += __shfl_xor_sync(0xffffffffu, v, o);
    int lane = threadIdx.x & 31;
    int wid  = threadIdx.x >> 5;
    if (lane == 0) sh[wid] = v;
    __syncthreads();
    if (threadIdx.x == 0) {
        float r = 0.f;
        #pragma unroll
        for (int w = 0; w < NT/32; w++) r += sh[w];
        sh[0] = r;
    }
    __syncthreads();
    float r = sh[0];
    __syncthreads();
    return r;
}

__device__ __forceinline__ float warpReduceSum(float v) {
    #pragma unroll
    for (int o = 16; o > 0; o >>= 1) v += __shfl_xor_sync(0xffffffffu, v, o);
    return v;
}

__device__ __forceinline__ float dot4(float4 a, float4 b) {
    return a.x*b.x + a.y*b.y + a.z*b.z + a.w*b.w;
}

__device__ __forceinline__ float ex2(float x) {
    float y;
    asm("ex2.approx.ftz.f32 %0, %1;" : "=f"(y) : "f"(x));
    return y;
}

__device__ __forceinline__ uint2 pack_bf16x4(float4 v) {
    __nv_bfloat162 lo = __floats2bfloat162_rn(v.x, v.y);
    __nv_bfloat162 hi = __floats2bfloat162_rn(v.z, v.w);
    uint2 u;
    u.x = *(uint32_t*)&lo;
    u.y = *(uint32_t*)&hi;
    return u;
}

#define CP_ASYNC16(dst, src) \
    asm volatile("cp.async.cg.shared.global [%0], [%1], 16;" :: "r"(dst), "l"(src))
#define CP_COMMIT() asm volatile("cp.async.commit_group;" ::: "memory")
#define CP_WAIT1()  asm volatile("cp.async.wait_group 1;"  ::: "memory")
#define CP_WAIT0()  asm volatile("cp.async.wait_group 0;"  ::: "memory")

static __device__ __forceinline__ uint32_t smem_u32(const void* p) {
    uint32_t a;
    asm("{ .reg .u64 t; cvta.to.shared.u64 t, %1; cvt.u32.u64 %0, t; }"
        : "=r"(a) : "l"(p));
    return a;
}

#define LDSM_X4(r0, r1, r2, r3, addr) \
    asm volatile("ldmatrix.sync.aligned.m8n8.x4.shared.b16 {%0,%1,%2,%3}, [%4];" \
                 : "=r"(r0), "=r"(r1), "=r"(r2), "=r"(r3) : "r"(addr))

__device__ __forceinline__ void mma_bf16(float& d0, float& d1, float& d2, float& d3,
                                         uint32_t a0, uint32_t a1, uint32_t a2, uint32_t a3,
                                         uint32_t b0, uint32_t b1) {
    asm volatile(
        "mma.sync.aligned.m16n8k16.row.col.f32.bf16.bf16.f32 "
        "{%0,%1,%2,%3}, {%4,%5,%6,%7}, {%8,%9}, {%0,%1,%2,%3};"
        : "+f"(d0), "+f"(d1), "+f"(d2), "+f"(d3)
        : "r"(a0), "r"(a1), "r"(a2), "r"(a3), "r"(b0), "r"(b1));
}

// ---------------- kernel 1: zero + normalize + gather + rho/diag prep --------
__global__ void __launch_bounds__(256) prep_kernel(
        const float* __restrict__ audio,
        const float* __restrict__ frame,
        const float* __restrict__ acent,
        const float* __restrict__ adens,
        const float* __restrict__ fcent,
        const float* __restrict__ fdens,
        const int*   __restrict__ vidx,
        const int*   __restrict__ ai2c,
        const int*   __restrict__ fi2c) {
    int gid = blockIdx.x * 256 + threadIdx.x;
    if (gid < B_) { g_rowsum[gid] = 0.f; g_colsum[gid] = 0.f; }
    if (gid < R_*B_) { g_psum_vf[gid] = 0.f; g_psum_fv[gid] = 0.f; }
    if (gid < 3) g_acc[gid] = 0.f;

    int w    = threadIdx.x >> 5;
    int lane = threadIdx.x & 31;
    int i    = blockIdx.x * 8 + w;

    const float4* a4 = (const float4*)(audio + (size_t)i*D_);
    const float4* f4 = (const float4*)(frame + (size_t)i*D_);
    float4 a[4], f[4];
    #pragma unroll
    for (int q = 0; q < 4; q++) { a[q] = a4[q*32 + lane]; f[q] = f4[q*32 + lane]; }

    float sa = 0.f, sf = 0.f, saf = 0.f;
    #pragma unroll
    for (int q = 0; q < 4; q++) {
        sa  += dot4(a[q], a[q]);
        sf  += dot4(f[q], f[q]);
        saf += dot4(a[q], f[q]);
    }
    sa = warpReduceSum(sa); sf = warpReduceSum(sf); saf = warpReduceSum(saf);

    float ascale = 1.f / fmaxf(sqrtf(sa), 1e-12f);
    float fscale = 1.f / fmaxf(sqrtf(sf), 1e-12f);

    uint2* anOut = (uint2*)(g_anorm + (size_t)i*D_);
    uint2* fnOut = (uint2*)(g_fnorm + (size_t)i*D_);
    #pragma unroll
    for (int q = 0; q < 4; q++) {
        anOut[q*32 + lane] = pack_bf16x4(make_float4(a[q].x*ascale, a[q].y*ascale,
                                                     a[q].z*ascale, a[q].w*ascale));
        fnOut[q*32 + lane] = pack_bf16x4(make_float4(f[q].x*fscale, f[q].y*fscale,
                                                     f[q].z*fscale, f[q].w*fscale));
    }

    float rho = saf * ascale * fscale;
    if (lane == 0) g_diag_vf[i] = rho * INV_T;

    int vi = vidx[i];
    #pragma unroll
    for (int r = 0; r < R_; r++) {
        int pa = ai2c[r*N_ + vi];
        int pf = fi2c[r*N_ + vi];
        const float4* ca4 = (const float4*)(acent + ((size_t)r*K_ + pa)*D_);
        const float4* cf4 = (const float4*)(fcent + ((size_t)r*K_ + pf)*D_);
        float4 ca[4], cf[4];
        #pragma unroll
        for (int q = 0; q < 4; q++) { ca[q] = ca4[q*32 + lane]; cf[q] = cf4[q*32 + lane]; }

        float c1 = 0.f, c2 = 0.f, c3 = 0.f, c4 = 0.f, c5 = 0.f;
        #pragma unroll
        for (int q = 0; q < 4; q++) {
            c1 += dot4(ca[q], ca[q]);
            c2 += dot4(cf[q], cf[q]);
            c3 += dot4(ca[q], cf[q]);
            c4 += dot4(a[q],  cf[q]);
            c5 += dot4(f[q],  ca[q]);
        }
        c1 = warpReduceSum(c1); c2 = warpReduceSum(c2); c3 = warpReduceSum(c3);
        c4 = warpReduceSum(c4); c5 = warpReduceSum(c5);

        float cascale = 1.f / fmaxf(sqrtf(c1), 1e-12f);
        float cfscale = 1.f / fmaxf(sqrtf(c2), 1e-12f);

        uint2* paOut = (uint2*)(g_Pa + ((size_t)r*B_ + i)*D_);
        uint2* pfOut = (uint2*)(g_Pf + ((size_t)r*B_ + i)*D_);
        #pragma unroll
        for (int q = 0; q < 4; q++) {
            paOut[q*32 + lane] = pack_bf16x4(make_float4(ca[q].x*cascale, ca[q].y*cascale,
                                                         ca[q].z*cascale, ca[q].w*cascale));
            pfOut[q*32 + lane] = pack_bf16x4(make_float4(cf[q].x*cfscale, cf[q].y*cfscale,
                                                         cf[q].z*cfscale, cf[q].w*cfscale));
        }

        rho -= c3;
        if (lane == 0) {
            float da = adens[r*K_ + pa];
            float df = fdens[r*K_ + pf];
            g_densa[r*B_ + i]    = da;
            g_densf[r*B_ + i]    = df;
            g_idensa[r*B_ + i]   = 1.f / da;
            g_idensf[r*B_ + i]   = 1.f / df;
            g_diagp_vf[r*B_ + i] = c4 * ascale * cfscale;
            g_diagp_fv[r*B_ + i] = c5 * fscale * cascale;
        }
    }
    if (lane == 0) g_rho[i] = rho;
}

// ---------------- kernel 2: bf16 mma.sync GEMM + fused exp-sum epilogue ------
// R10-winning config: 128x128 CTA tile, 8 warps 2(M)x4(N), warp tile 64x32,
// BK=64 (NCHUNK=8), 3-stage cp.async pipeline, SINGLE __syncthreads per chunk.
// Only change vs R10: raw ex2.approx.ftz in the epilogue (guaranteed 1 MUFU).
#define TM 128
#define TN 128
#define BK 64
#define NCHUNK (D_/BK)
#define SROWB 144

#define SZ_A (TM*SROWB)                // 18432
#define SZ_B (TN*SROWB)                // 18432
#define SZ_STAGE (SZ_A + SZ_B)         // 36864
#define SO_DENS (3*SZ_STAGE)
#define GEMM_SMEM (SO_DENS + 132*4)

__device__ __forceinline__ void load_stage(uint32_t stBase,
                                           const __nv_bfloat16* __restrict__ A,
                                           const __nv_bfloat16* __restrict__ Bm,
                                           int rowBase, int colBase, int k0, int t) {
    uint32_t aBase = stBase;
    uint32_t bBase = stBase + SZ_A;
    #pragma unroll
    for (int q = 0; q < 4; q++) {
        int slot = t + q*256;
        int r = slot >> 3, s = slot & 7;
        CP_ASYNC16(aBase + r*SROWB + s*16,
                   A + (size_t)(rowBase + r)*D_ + k0 + s*8);
    }
    #pragma unroll
    for (int q = 0; q < 4; q++) {
        int slot = t + q*256;
        int r = slot >> 3, s = slot & 7;
        CP_ASYNC16(bBase + r*SROWB + s*16,
                   Bm + (size_t)(colBase + r)*D_ + k0 + s*8);
    }
}

__global__ void __launch_bounds__(256) gemm_kernel() {
    extern __shared__ char smem[];
    uint32_t sb = smem_u32(smem);
    int t    = threadIdx.x;
    int wid  = t >> 5;
    int lane = t & 31;
    int g    = lane >> 2;
    int tq   = lane & 3;

    int z = blockIdx.z;
    const __nv_bfloat16 *A, *Bm;
    const float *idens = nullptr;
    float *rowAcc;
    if (z == 0)      { A = g_anorm; Bm = g_fnorm; rowAcc = g_rowsum; }
    else if (z <= 3) { int r = z-1; A = g_anorm; Bm = g_Pf + (size_t)r*B_*D_;
                       idens = g_idensf + r*B_; rowAcc = g_psum_vf + r*B_; }
    else             { int r = z-4; A = g_fnorm; Bm = g_Pa + (size_t)r*B_*D_;
                       idens = g_idensa + r*B_; rowAcc = g_psum_fv + r*B_; }

    int rowBase = blockIdx.y * TM;
    int colBase = blockIdx.x * TN;
    int mbase = (wid & 1) * 64;
    int nbase = (wid >> 1) * 32;

    int lq = lane >> 3, lr = lane & 7;
    uint32_t aOff[4];
    #pragma unroll
    for (int Mt = 0; Mt < 4; Mt++)
        aOff[Mt] = (mbase + Mt*16 + (lq & 1)*8 + lr)*SROWB + (lq >> 1)*16;
    uint32_t bOff[2];
    #pragma unroll
    for (int p = 0; p < 2; p++)
        bOff[p] = SZ_A + (nbase + p*16 + (lq >> 1)*8 + lr)*SROWB + (lq & 1)*16;

    float acc[4][4][4];
    #pragma unroll
    for (int i = 0; i < 4; i++)
        #pragma unroll
        for (int j = 0; j < 4; j++) {
            acc[i][j][0] = 0.f; acc[i][j][1] = 0.f;
            acc[i][j][2] = 0.f; acc[i][j][3] = 0.f;
        }

    load_stage(sb + 0*SZ_STAGE, A, Bm, rowBase, colBase, 0,  t);
    CP_COMMIT();
    load_stage(sb + 1*SZ_STAGE, A, Bm, rowBase, colBase, BK, t);
    CP_COMMIT();

    #pragma unroll 1
    for (int c = 0; c < NCHUNK; c++) {
        int st = c % 3;
        CP_WAIT1();
        __syncthreads();
        uint32_t stB = sb + st*SZ_STAGE;

        #pragma unroll
        for (int ks = 0; ks < 4; ks++) {
            uint32_t af[4][4], bf[2][4];
            #pragma unroll
            for (int Mt = 0; Mt < 4; Mt++)
                LDSM_X4(af[Mt][0], af[Mt][1], af[Mt][2], af[Mt][3],
                        stB + aOff[Mt] + ks*32);
            #pragma unroll
            for (int p = 0; p < 2; p++)
                LDSM_X4(bf[p][0], bf[p][1], bf[p][2], bf[p][3],
                        stB + bOff[p] + ks*32);
            #pragma unroll
            for (int Mt = 0; Mt < 4; Mt++)
                #pragma unroll
                for (int Nt = 0; Nt < 4; Nt++)
                    mma_bf16(acc[Mt][Nt][0], acc[Mt][Nt][1],
                             acc[Mt][Nt][2], acc[Mt][Nt][3],
                             af[Mt][0], af[Mt][1], af[Mt][2], af[Mt][3],
                             bf[Nt>>1][(Nt&1)*2], bf[Nt>>1][(Nt&1)*2 + 1]);
        }
        if (c + 2 < NCHUNK) {
            load_stage(sb + ((c + 2) % 3)*SZ_STAGE, A, Bm,
                       rowBase, colBase, (c + 2)*BK, t);
        }
        CP_COMMIT();   // unconditional: uniform group accounting
    }
    CP_WAIT0();

    float* sdens = (float*)(smem + SO_DENS);
    float d0inv = 0.f;
    if (z != 0) {
        for (int i = t; i < TN + 2; i += 256) {
            int gidx = colBase + i;
            sdens[i] = (gidx < B_) ? idens[gidx] * LOG2E : 1.f;
        }
        d0inv = idens[0] * LOG2E;
    }
    __syncthreads();

    // ---------------- epilogue -----------------------------------------------
    if (z == 0) {
        const float k1 = INV_T * LOG2E;
        float rowp[4][2] = {};
        float colp[4][2] = {};
        #pragma unroll
        for (int Mt = 0; Mt < 4; Mt++)
            #pragma unroll
            for (int Nt = 0; Nt < 4; Nt++) {
                float e00 = ex2(acc[Mt][Nt][0] * k1);
                float e01 = ex2(acc[Mt][Nt][1] * k1);
                float e10 = ex2(acc[Mt][Nt][2] * k1);
                float e11 = ex2(acc[Mt][Nt][3] * k1);
                rowp[Mt][0] += e00 + e01;
                rowp[Mt][1] += e10 + e11;
                colp[Nt][0] += e00 + e10;
                colp[Nt][1] += e01 + e11;
            }
        #pragma unroll
        for (int Mt = 0; Mt < 4; Mt++)
            #pragma unroll
            for (int h = 0; h < 2; h++) {
                float v = rowp[Mt][h];
                v += __shfl_xor_sync(0xffffffffu, v, 1);
                v += __shfl_xor_sync(0xffffffffu, v, 2);
                if (tq == 0)
                    atomicAdd(&rowAcc[rowBase + mbase + Mt*16 + g + h*8], v);
            }
        #pragma unroll
        for (int Nt = 0; Nt < 4; Nt++)
            #pragma unroll
            for (int h = 0; h < 2; h++) {
                float v = colp[Nt][h];
                v += __shfl_xor_sync(0xffffffffu, v, 4);
                v += __shfl_xor_sync(0xffffffffu, v, 8);
                v += __shfl_xor_sync(0xffffffffu, v, 16);
                if (g == 0)
                    atomicAdd(&g_colsum[colBase + nbase + Nt*8 + 2*tq + h], v);
            }
    } else {
        float rowp[4][2] = {};
        #pragma unroll
        for (int Mt = 0; Mt < 4; Mt++) {
            int r0 = rowBase + mbase + Mt*16 + g;
            int r1 = r0 + 8;
            #pragma unroll
            for (int Nt = 0; Nt < 4; Nt++) {
                int lc = nbase + Nt*8 + 2*tq;
                int c0 = colBase + lc;
                int c1 = c0 + 1;
                float i00 = (c0 < r0) ? sdens[lc+1] : ((c0 > r0) ? sdens[lc]   : d0inv);
                float i01 = (c1 < r0) ? sdens[lc+2] : ((c1 > r0) ? sdens[lc+1] : d0inv);
                float i10 = (c0 < r1) ? sdens[lc+1] : ((c0 > r1) ? sdens[lc]   : d0inv);
                float i11 = (c1 < r1) ? sdens[lc+2] : ((c1 > r1) ? sdens[lc+1] : d0inv);
                rowp[Mt][0] += ex2(acc[Mt][Nt][0] * i00) + ex2(acc[Mt][Nt][1] * i01);
                rowp[Mt][1] += ex2(acc[Mt][Nt][2] * i10) + ex2(acc[Mt][Nt][3] * i11);
            }
        }
        #pragma unroll
        for (int Mt = 0; Mt < 4; Mt++)
            #pragma unroll
            for (int h = 0; h < 2; h++) {
                float v = rowp[Mt][h];
                v += __shfl_xor_sync(0xffffffffu, v, 1);
                v += __shfl_xor_sync(0xffffffffu, v, 2);
                if (tq == 0)
                    atomicAdd(&rowAcc[rowBase + mbase + Mt*16 + g + h*8], v);
            }
    }
}

// ---------------- kernel 3: stats + pdf + rank-cumsum weights (warp/row) -----
__global__ void __launch_bounds__(256) weight_kernel() {
    __shared__ float srho[B_];
    __shared__ float sp[B_];
    __shared__ float sh[8];
    int t = threadIdx.x;

    for (int j = t; j < B_; j += 256) srho[j] = g_rho[j];
    __syncthreads();

    float s = 0.f, s2 = 0.f;
    for (int j = t; j < B_; j += 256) {
        float v = srho[j];
        s += v; s2 += v*v;
    }
    s  = blockReduceSum<256>(s,  sh);
    s2 = blockReduceSum<256>(s2, sh);
    float mean = s / (float)B_;
    float var  = fmaxf(s2 / (float)B_ - mean*mean, 0.f);
    float sd   = sqrtf(var);
    float mu    = mean + 0.3f * sd;
    float sigma = sd * sqrtf(2.0f);

    for (int j = t; j < B_; j += 256) {
        float zq = (srho[j] - mu) / sigma;
        sp[j] = ex2(-0.5f * LOG2E * zq * zq);
    }
    __syncthreads();

    int w    = t >> 5;
    int lane = t & 31;
    int i    = blockIdx.x * 8 + w;
    float ri = srho[i];
    float acc = 0.f;
    for (int j = lane; j < B_; j += 32) {
        float rj = srho[j];
        if (rj < ri || (rj == ri && j <= i)) acc += sp[j];
    }
    acc = warpReduceSum(acc);
    if (lane == 0) g_w[i] = acc;
}

// ---------------- kernel 4: assemble losses + weighted partial reduction -----
__global__ void __launch_bounds__(256) final_kernel() {
    __shared__ float sh[8];
    const float coef0 = 1.f/27.f, coef1 = 1.f/9.f, coef2 = 1.f/3.f;
    int i = blockIdx.x * 256 + threadIdx.x;

    float ii_vf = logf(g_rowsum[i]) - g_diag_vf[i];
    float ii_fv = logf(g_colsum[i]) - g_diag_vf[i];
    float ip_vf =
        coef0 * (logf(g_psum_vf[0*B_+i]) - g_diagp_vf[0*B_+i] / g_densf[0*B_]) +
        coef1 * (logf(g_psum_vf[1*B_+i]) - g_diagp_vf[1*B_+i] / g_densf[1*B_]) +
        coef2 * (logf(g_psum_vf[2*B_+i]) - g_diagp_vf[2*B_+i] / g_densf[2*B_]);
    float ip_fv =
        coef0 * (logf(g_psum_fv[0*B_+i]) - g_diagp_fv[0*B_+i] / g_densa[0*B_]) +
        coef1 * (logf(g_psum_fv[1*B_+i]) - g_diagp_fv[1*B_+i] / g_densa[1*B_]) +
        coef2 * (logf(g_psum_fv[2*B_+i]) - g_diagp_fv[2*B_+i] / g_densa[2*B_]);
    float w = g_w[i];
    float sw  = blockReduceSum<256>(w, sh);
    float svf = blockReduceSum<256>(w * (ii_vf + ip_vf), sh);
    float sfv = blockReduceSum<256>(w * (ii_fv + ip_fv), sh);
    if (threadIdx.x == 0) {
        atomicAdd(&g_acc[0], sw);
        atomicAdd(&g_acc[1], svf);
        atomicAdd(&g_acc[2], sfv);
    }
}

__global__ void finalize_kernel(float* __restrict__ out) {
    if (threadIdx.x == 0)
        out[0] = g_acc[1] / g_acc[0] + g_acc[2] / g_acc[0];
}

// ---------------- launch -----------------------------------------------------
extern "C" void kernel_launch(void* const* d_in, const int* in_sizes, int n_in,
                              void* d_out, int out_size) {
    const float* audio = (const float*)d_in[0];
    const float* frame = (const float*)d_in[1];
    const float* acent = (const float*)d_in[2];
    const float* adens = (const float*)d_in[3];
    const float* fcent = (const float*)d_in[4];
    const float* fdens = (const float*)d_in[5];
    const int*   vidx  = (const int*)d_in[6];
    const int*   ai2c  = (const int*)d_in[7];
    const int*   fi2c  = (const int*)d_in[8];
    float* out = (float*)d_out;
    (void)in_sizes; (void)n_in; (void)out_size;

    cudaFuncSetAttribute(gemm_kernel,
                         cudaFuncAttributeMaxDynamicSharedMemorySize, GEMM_SMEM);

    prep_kernel<<<B_/8, 256>>>(audio, frame, acent, adens, fcent, fdens,
                               vidx, ai2c, fi2c);
    weight_kernel<<<B_/8, 256>>>();
    dim3 g(B_/TN, B_/TM, 7);
    gemm_kernel<<<g, 256, GEMM_SMEM>>>();
    final_kernel<<<B_/256, 256>>>();
    finalize_kernel<<<1, 32>>>(out);
}